// round 12
// baseline (speedup 1.0000x reference)
#include <cuda_runtime.h>
#include <cstddef>
#include <cstdint>

#define EPS 1e-8f

static constexpr int B    = 1024;
static constexpr int K    = 512;
static constexpr int E    = 64;
static constexpr int D    = 769;
static constexpr int TOPK = 64;

typedef unsigned long long u64;

__device__ float g_aw[B * E];
__device__ float g_la[B * E];
__device__ float g_scores[B * K];
__device__ int   g_idx[B * TOPK];

// ---------------------------------------------------------------------------
// Packed primitives — ALL routed through fma.rn.f32x2 (SASS FFMA2, rt=2).
// add(a,b)  == fma(a, 1, b)   (bitwise identical: rn(a*1+b) = rn(a+b))
// mul(a,b)  == fma(a, b, +0)  (identical except ab==-0 -> +0; audited safe)
// ---------------------------------------------------------------------------
__device__ __forceinline__ u64 pk2(float lo, float hi) {
    u64 r; asm("mov.b64 %0, {%1, %2};" : "=l"(r) : "f"(lo), "f"(hi)); return r;
}
__device__ __forceinline__ void upk2(u64 v, float& lo, float& hi) {
    asm("mov.b64 {%0, %1}, %2;" : "=f"(lo), "=f"(hi) : "l"(v));
}
__device__ __forceinline__ u64 fma2(u64 a, u64 b, u64 c) {
    u64 r; asm("fma.rn.f32x2 %0, %1, %2, %3;" : "=l"(r) : "l"(a), "l"(b), "l"(c)); return r;
}
#define ONE2  0x3F8000003F800000ull
#define ZERO2 0x0000000000000000ull
__device__ __forceinline__ u64 add2(u64 a, u64 b) { return fma2(a, ONE2, b); }
__device__ __forceinline__ u64 mul2(u64 a, u64 b) { return fma2(a, b, ZERO2); }

// ---------------------------------------------------------------------------
// Scalar XLA-CPU log (Eigen plog / Cephes, no FMA) — proven. Anchor only.
// ---------------------------------------------------------------------------
__device__ __forceinline__ float xla_logf(float xin) {
    float x = fmaxf(xin, __uint_as_float(0x00800000u));
    uint32_t bits = __float_as_uint(x);
    int emm0 = (int)(bits >> 23) - 126;
    float e = (float)emm0;
    float m = __uint_as_float((bits & 0x807fffffu) | 0x3f000000u);
    bool mask = m < __uint_as_float(0x3f3504f3u);
    float tmp = mask ? m : 0.0f;
    float xx = __fadd_rn(__fsub_rn(m, 1.0f), tmp);
    e = __fsub_rn(e, mask ? 1.0f : 0.0f);

    float z = __fmul_rn(xx, xx);
    float y = 7.0376836292e-2f;
    y = __fadd_rn(__fmul_rn(y, xx), -1.1514610310e-1f);
    y = __fadd_rn(__fmul_rn(y, xx),  1.1676998740e-1f);
    y = __fadd_rn(__fmul_rn(y, xx), -1.2420140846e-1f);
    y = __fadd_rn(__fmul_rn(y, xx),  1.4249322787e-1f);
    y = __fadd_rn(__fmul_rn(y, xx), -1.6668057665e-1f);
    y = __fadd_rn(__fmul_rn(y, xx),  2.0000714765e-1f);
    y = __fadd_rn(__fmul_rn(y, xx), -2.4999993993e-1f);
    y = __fadd_rn(__fmul_rn(y, xx),  3.3333331174e-1f);
    y = __fmul_rn(y, xx);
    y = __fmul_rn(y, z);
    y = __fadd_rn(y, __fmul_rn(e, -2.12194440e-4f));
    y = __fsub_rn(y, __fmul_rn(z, 0.5f));
    float r = __fadd_rn(xx, y);
    r = __fadd_rn(r, __fmul_rn(e, 0.693359375f));
    return r;
}

// ---------------------------------------------------------------------------
// Packed XLA-CPU log, all-FFMA2. Bitwise identical per lane to xla_logf for
// our inputs (>= 1e-8, normal). Exact fusions used:
//   y - z*0.5      == fma(z, -0.5, y)         (z*0.5 exact)
//   r + e*ln2hi    == fma(e, ln2hi, r)        (e*0.693359375 exact: 9-bit c)
//   e*(-2.12e-4)   stays mul-then-add         (product inexact)
// ---------------------------------------------------------------------------
__device__ __forceinline__ u64 xla_logf_x2(u64 x01) {
    float x0, x1; upk2(x01, x0, x1);
    uint32_t b0 = __float_as_uint(x0), b1 = __float_as_uint(x1);
    int e0i = (int)(b0 >> 23) - 126;
    int e1i = (int)(b1 >> 23) - 126;
    float m0 = __uint_as_float((b0 & 0x807fffffu) | 0x3f000000u);
    float m1 = __uint_as_float((b1 & 0x807fffffu) | 0x3f000000u);
    const float SQ = __uint_as_float(0x3f3504f3u);
    bool k0 = m0 < SQ, k1 = m1 < SQ;
    float t0 = k0 ? m0 : 0.0f;
    float t1 = k1 ? m1 : 0.0f;
    if (k0) e0i -= 1;
    if (k1) e1i -= 1;
    u64 m01 = pk2(m0, m1);
    u64 t01 = pk2(t0, t1);
    u64 e01 = pk2((float)e0i, (float)e1i);

    u64 xx = add2(add2(m01, pk2(-1.0f, -1.0f)), t01);
    u64 z  = mul2(xx, xx);
    u64 y  = pk2(7.0376836292e-2f, 7.0376836292e-2f);
    y = add2(mul2(y, xx), pk2(-1.1514610310e-1f, -1.1514610310e-1f));
    y = add2(mul2(y, xx), pk2( 1.1676998740e-1f,  1.1676998740e-1f));
    y = add2(mul2(y, xx), pk2(-1.2420140846e-1f, -1.2420140846e-1f));
    y = add2(mul2(y, xx), pk2( 1.4249322787e-1f,  1.4249322787e-1f));
    y = add2(mul2(y, xx), pk2(-1.6668057665e-1f, -1.6668057665e-1f));
    y = add2(mul2(y, xx), pk2( 2.0000714765e-1f,  2.0000714765e-1f));
    y = add2(mul2(y, xx), pk2(-2.4999993993e-1f, -2.4999993993e-1f));
    y = add2(mul2(y, xx), pk2( 3.3333331174e-1f,  3.3333331174e-1f));
    y = mul2(y, xx);
    y = mul2(y, z);
    y = add2(y, mul2(e01, pk2(-2.12194440e-4f, -2.12194440e-4f)));
    y = fma2(z, pk2(-0.5f, -0.5f), y);              // exact fusion
    u64 r = add2(xx, y);
    r = fma2(e01, pk2(0.693359375f, 0.693359375f), r);  // exact fusion
    return r;
}

#define NEON_HORIZ(a0, a1, a2, a3) __fadd_rn(__fadd_rn(a0, a2), __fadd_rn(a1, a3))

// ---------------------------------------------------------------------------
// K1: anchor rows (scalar, proven, unchanged).
// ---------------------------------------------------------------------------
__global__ __launch_bounds__(256) void k_anchor(const float* __restrict__ anchor) {
    int b = blockIdx.x * blockDim.x + threadIdx.x;
    if (b >= B) return;
    const float4* row = (const float4*)(anchor + b * E);
    float4 vv[16];
    float a0 = 0.f, a1 = 0.f, a2 = 0.f, a3 = 0.f;
    #pragma unroll
    for (int c = 0; c < 16; c++) {
        vv[c] = __ldg(row + c);
        a0 = __fadd_rn(a0, __fadd_rn(vv[c].x, EPS));
        a1 = __fadd_rn(a1, __fadd_rn(vv[c].y, EPS));
        a2 = __fadd_rn(a2, __fadd_rn(vv[c].z, EPS));
        a3 = __fadd_rn(a3, __fadd_rn(vv[c].w, EPS));
    }
    float S = NEON_HORIZ(a0, a1, a2, a3);
    const float* vf = (const float*)vv;
    #pragma unroll
    for (int e = 0; e < E; e++) {
        float a = __fdiv_rn(__fadd_rn(vf[e], EPS), S);
        g_aw[b * E + e] = a;
        g_la[b * E + e] = xla_logf(__fadd_rn(a, EPS));
    }
}

// ---------------------------------------------------------------------------
// K2: confusion scores, all-FFMA2 packed. Arithmetic identical to R11
// (Markstein CR division, packed Cephes log, NEON reduce).
// ---------------------------------------------------------------------------
__global__ __launch_bounds__(256, 3) void k_scores(const float* __restrict__ neg) {
    __shared__ u64 s_a64[E / 2], s_la64[E / 2];
    int b = blockIdx.x >> 1;
    int k = ((blockIdx.x & 1) << 8) + threadIdx.x;
    if (threadIdx.x < E / 2) {
        const float* pa = &g_aw[b * E + 2 * threadIdx.x];
        const float* pl = &g_la[b * E + 2 * threadIdx.x];
        s_a64[threadIdx.x]  = pk2(__ldg(pa), __ldg(pa + 1));
        s_la64[threadIdx.x] = pk2(__ldg(pl), __ldg(pl + 1));
    }
    __syncthreads();

    const u64* row = (const u64*)(neg + ((size_t)b * K + k) * E);
    const u64 EPS2 = pk2(EPS, EPS);

    // pass 1: row sum (packed accumulators; asm loads avoid CSE with pass 2)
    u64 acc01 = ZERO2, acc23 = ZERO2;
    #pragma unroll
    for (int c = 0; c < 16; c++) {
        u64 r01, r23;
        asm volatile("ld.global.nc.v2.u64 {%0, %1}, [%2];"
                     : "=l"(r01), "=l"(r23) : "l"(row + 2 * c));
        acc01 = add2(acc01, add2(r01, EPS2));
        acc23 = add2(acc23, add2(r23, EPS2));
    }
    float h02, h13;
    upk2(add2(acc01, acc23), h02, h13);
    float S = __fadd_rn(h02, h13);

    float yr = __frcp_rn(S);
    const u64 yy    = pk2(yr, yr);
    const u64 negS2 = pk2(-S, -S);
    const u64 NEG1  = pk2(-1.0f, -1.0f);

    // pass 2: KL accumulation (packed)
    u64 k01 = ZERO2, k23 = ZERO2;
    #pragma unroll 4
    for (int c = 0; c < 16; c++) {
        ulonglong2 rv = __ldg((const ulonglong2*)(row + 2 * c));
        u64 ne01 = add2(rv.x, EPS2);
        u64 ne23 = add2(rv.y, EPS2);
        // Markstein correctly-rounded division by S
        u64 q01 = mul2(ne01, yy);
        q01 = fma2(fma2(negS2, q01, ne01), yy, q01);
        u64 q23 = mul2(ne23, yy);
        q23 = fma2(fma2(negS2, q23, ne23), yy, q23);

        u64 ln01 = xla_logf_x2(add2(q01, EPS2));
        u64 ln23 = xla_logf_x2(add2(q23, EPS2));

        // d = la - ln == fma(ln, -1, la)   ((-1)*ln exact inside fma)
        u64 d01 = fma2(ln01, NEG1, s_la64[2 * c]);
        u64 d23 = fma2(ln23, NEG1, s_la64[2 * c + 1]);
        k01 = add2(k01, mul2(s_a64[2 * c],     d01));
        k23 = add2(k23, mul2(s_a64[2 * c + 1], d23));
    }
    float g02, g13;
    upk2(add2(k01, k23), g02, g13);
    g_scores[b * K + k] = -__fadd_rn(g02, g13);
}

// ---------------------------------------------------------------------------
// K3: per-row top-64 via bitonic sort of 512 (desc, ties -> lower index).
// ---------------------------------------------------------------------------
__global__ __launch_bounds__(512) void k_topk(float* __restrict__ out_scores) {
    __shared__ float ss[K];
    __shared__ int   si[K];
    int b = blockIdx.x, tid = threadIdx.x;
    ss[tid] = g_scores[b * K + tid];
    si[tid] = tid;
    for (int sz = 2; sz <= K; sz <<= 1) {
        for (int j = sz >> 1; j > 0; j >>= 1) {
            __syncthreads();
            int ixj = tid ^ j;
            if (ixj > tid) {
                bool desc = ((tid & sz) == 0);
                float s1 = ss[tid], s2 = ss[ixj];
                int   i1 = si[tid], i2 = si[ixj];
                bool g = (s1 > s2) || (s1 == s2 && i1 < i2);
                if (g != desc) {
                    ss[tid] = s2; ss[ixj] = s1;
                    si[tid] = i2; si[ixj] = i1;
                }
            }
        }
    }
    __syncthreads();
    if (tid < TOPK) {
        out_scores[b * TOPK + tid] = ss[tid];
        g_idx[b * TOPK + tid]      = si[tid];
    }
}

// ---------------------------------------------------------------------------
// K4: vectorized gather (float4 + per-warp smem realign; proven bit-exact in
// R10). One warp per output row; CTA = 4 warps; grid = B*16.
// ---------------------------------------------------------------------------
__global__ __launch_bounds__(128) void k_gather(
    const float* __restrict__ cand, float* __restrict__ out_hard)
{
    __shared__ float buf[4][776];
    int blk  = blockIdx.x;
    int b    = blk >> 4;
    int warp = threadIdx.x >> 5, lane = threadIdx.x & 31;
    int j    = ((blk & 15) << 2) + warp;

    int sidx = g_idx[b * TOPK + j];
    size_t sbase = ((size_t)b * K + sidx) * D;
    int m_s = sidx & 3;                       // (b*512+sidx)*769 mod 4
    const float4* f4src = (const float4*)(cand + sbase - m_s);
    #pragma unroll
    for (int c4 = lane; c4 < 192; c4 += 32)
        *(float4*)&buf[warp][4 * c4] = __ldg(f4src + c4);
    if (lane <= m_s)
        buf[warp][768 + lane] = __ldg(cand + sbase + 768 - m_s + lane);
    __syncwarp();

    float* dst = out_hard + ((size_t)b * TOPK + j) * D;
    int m_d = j & 3;                          // (b*64+j)*769 mod 4
    int h = (4 - m_d) & 3;
    if (lane < h) dst[lane] = buf[warp][lane + m_s];
    int nd4 = (D - h) >> 2;
    float4* f4dst = (float4*)(dst + h);
    #pragma unroll
    for (int c4 = lane; c4 < nd4; c4 += 32) {
        int e0 = h + 4 * c4 + m_s;
        float4 v = { buf[warp][e0],     buf[warp][e0 + 1],
                     buf[warp][e0 + 2], buf[warp][e0 + 3] };
        f4dst[c4] = v;
    }
    int rem = (D - h) & 3;
    if (lane < rem) {
        int e = h + 4 * nd4 + lane;
        dst[e] = buf[warp][e + m_s];
    }
}

// ---------------------------------------------------------------------------
extern "C" void kernel_launch(void* const* d_in, const int* in_sizes, int n_in,
                              void* d_out, int out_size) {
    const float* anchor = (const float*)d_in[0];  // (B, E)
    const float* neg    = (const float*)d_in[1];  // (B, K, E)
    const float* cand   = (const float*)d_in[2];  // (B, K, D)
    float* out        = (float*)d_out;
    float* out_hard   = out;                          // (B, TOPK, D)
    float* out_scores = out + (size_t)B * TOPK * D;   // (B, TOPK)

    k_anchor<<<4, 256>>>(anchor);
    k_scores<<<B * 2, 256>>>(neg);
    k_topk<<<B, 512>>>(out_scores);
    k_gather<<<B * 16, 128>>>(cand, out_hard);
}

// round 13
// speedup vs baseline: 1.1281x; 1.1281x over previous
#include <cuda_runtime.h>
#include <cstddef>
#include <cstdint>

#define EPS 1e-8f

static constexpr int B    = 1024;
static constexpr int K    = 512;
static constexpr int E    = 64;
static constexpr int D    = 769;
static constexpr int TOPK = 64;

typedef unsigned long long u64;

__device__ float g_aw[B * E];
__device__ float g_la[B * E];
__device__ float g_scores[B * K];
__device__ int   g_idx[B * TOPK];

// ---------------------------------------------------------------------------
// Packed f32x2 primitives — each is two independent IEEE rn f32 ops,
// bit-identical per lane to scalar __fadd_rn/__fmul_rn/fmaf.
// ---------------------------------------------------------------------------
__device__ __forceinline__ u64 pk2(float lo, float hi) {
    u64 r; asm("mov.b64 %0, {%1, %2};" : "=l"(r) : "f"(lo), "f"(hi)); return r;
}
__device__ __forceinline__ void upk2(u64 v, float& lo, float& hi) {
    asm("mov.b64 {%0, %1}, %2;" : "=f"(lo), "=f"(hi) : "l"(v));
}
__device__ __forceinline__ u64 add2(u64 a, u64 b) {
    u64 r; asm("add.rn.f32x2 %0, %1, %2;" : "=l"(r) : "l"(a), "l"(b)); return r;
}
__device__ __forceinline__ u64 mul2(u64 a, u64 b) {
    u64 r; asm("mul.rn.f32x2 %0, %1, %2;" : "=l"(r) : "l"(a), "l"(b)); return r;
}
__device__ __forceinline__ u64 fma2(u64 a, u64 b, u64 c) {
    u64 r; asm("fma.rn.f32x2 %0, %1, %2, %3;" : "=l"(r) : "l"(a), "l"(b), "l"(c)); return r;
}

// ---------------------------------------------------------------------------
// Scalar XLA-CPU log (Eigen plog / Cephes, no FMA) — proven. Anchor only.
// DO NOT MODIFY.
// ---------------------------------------------------------------------------
__device__ __forceinline__ float xla_logf(float xin) {
    float x = fmaxf(xin, __uint_as_float(0x00800000u));
    uint32_t bits = __float_as_uint(x);
    int emm0 = (int)(bits >> 23) - 126;
    float e = (float)emm0;
    float m = __uint_as_float((bits & 0x807fffffu) | 0x3f000000u);
    bool mask = m < __uint_as_float(0x3f3504f3u);
    float tmp = mask ? m : 0.0f;
    float xx = __fadd_rn(__fsub_rn(m, 1.0f), tmp);
    e = __fsub_rn(e, mask ? 1.0f : 0.0f);

    float z = __fmul_rn(xx, xx);
    float y = 7.0376836292e-2f;
    y = __fadd_rn(__fmul_rn(y, xx), -1.1514610310e-1f);
    y = __fadd_rn(__fmul_rn(y, xx),  1.1676998740e-1f);
    y = __fadd_rn(__fmul_rn(y, xx), -1.2420140846e-1f);
    y = __fadd_rn(__fmul_rn(y, xx),  1.4249322787e-1f);
    y = __fadd_rn(__fmul_rn(y, xx), -1.6668057665e-1f);
    y = __fadd_rn(__fmul_rn(y, xx),  2.0000714765e-1f);
    y = __fadd_rn(__fmul_rn(y, xx), -2.4999993993e-1f);
    y = __fadd_rn(__fmul_rn(y, xx),  3.3333331174e-1f);
    y = __fmul_rn(y, xx);
    y = __fmul_rn(y, z);
    y = __fadd_rn(y, __fmul_rn(e, -2.12194440e-4f));
    y = __fsub_rn(y, __fmul_rn(z, 0.5f));
    float r = __fadd_rn(xx, y);
    r = __fadd_rn(r, __fmul_rn(e, 0.693359375f));
    return r;
}

// ---------------------------------------------------------------------------
// Packed XLA-CPU log (R11 form, measured best): bit-identical per lane to
// xla_logf for our inputs (>= 1e-8, normal; fmax clamp an identity, dropped).
// ---------------------------------------------------------------------------
__device__ __forceinline__ u64 xla_logf_x2(u64 x01) {
    float x0, x1; upk2(x01, x0, x1);
    uint32_t b0 = __float_as_uint(x0), b1 = __float_as_uint(x1);
    int e0i = (int)(b0 >> 23) - 126;
    int e1i = (int)(b1 >> 23) - 126;
    float m0 = __uint_as_float((b0 & 0x807fffffu) | 0x3f000000u);
    float m1 = __uint_as_float((b1 & 0x807fffffu) | 0x3f000000u);
    const float SQ = __uint_as_float(0x3f3504f3u);
    bool k0 = m0 < SQ, k1 = m1 < SQ;
    float t0 = k0 ? m0 : 0.0f;
    float t1 = k1 ? m1 : 0.0f;
    if (k0) e0i -= 1;
    if (k1) e1i -= 1;
    u64 m01 = pk2(m0, m1);
    u64 t01 = pk2(t0, t1);
    u64 e01 = pk2((float)e0i, (float)e1i);

    u64 xx = add2(add2(m01, pk2(-1.0f, -1.0f)), t01);
    u64 z  = mul2(xx, xx);
    u64 y  = pk2(7.0376836292e-2f, 7.0376836292e-2f);
    y = add2(mul2(y, xx), pk2(-1.1514610310e-1f, -1.1514610310e-1f));
    y = add2(mul2(y, xx), pk2( 1.1676998740e-1f,  1.1676998740e-1f));
    y = add2(mul2(y, xx), pk2(-1.2420140846e-1f, -1.2420140846e-1f));
    y = add2(mul2(y, xx), pk2( 1.4249322787e-1f,  1.4249322787e-1f));
    y = add2(mul2(y, xx), pk2(-1.6668057665e-1f, -1.6668057665e-1f));
    y = add2(mul2(y, xx), pk2( 2.0000714765e-1f,  2.0000714765e-1f));
    y = add2(mul2(y, xx), pk2(-2.4999993993e-1f, -2.4999993993e-1f));
    y = add2(mul2(y, xx), pk2( 3.3333331174e-1f,  3.3333331174e-1f));
    y = mul2(y, xx);
    y = mul2(y, z);
    y = add2(y, mul2(e01, pk2(-2.12194440e-4f, -2.12194440e-4f)));
    y = add2(y, mul2(z,   pk2(-0.5f, -0.5f)));
    u64 r = add2(xx, y);
    r = add2(r, mul2(e01, pk2(0.693359375f, 0.693359375f)));
    return r;
}

#define NEON_HORIZ(a0, a1, a2, a3) __fadd_rn(__fadd_rn(a0, a2), __fadd_rn(a1, a3))

// ---------------------------------------------------------------------------
// K1: anchor rows (scalar, proven, unchanged).
// ---------------------------------------------------------------------------
__global__ __launch_bounds__(256) void k_anchor(const float* __restrict__ anchor) {
    int b = blockIdx.x * blockDim.x + threadIdx.x;
    if (b >= B) return;
    const float4* row = (const float4*)(anchor + b * E);
    float4 vv[16];
    float a0 = 0.f, a1 = 0.f, a2 = 0.f, a3 = 0.f;
    #pragma unroll
    for (int c = 0; c < 16; c++) {
        vv[c] = __ldg(row + c);
        a0 = __fadd_rn(a0, __fadd_rn(vv[c].x, EPS));
        a1 = __fadd_rn(a1, __fadd_rn(vv[c].y, EPS));
        a2 = __fadd_rn(a2, __fadd_rn(vv[c].z, EPS));
        a3 = __fadd_rn(a3, __fadd_rn(vv[c].w, EPS));
    }
    float S = NEON_HORIZ(a0, a1, a2, a3);
    const float* vf = (const float*)vv;
    #pragma unroll
    for (int e = 0; e < E; e++) {
        float a = __fdiv_rn(__fadd_rn(vf[e], EPS), S);
        g_aw[b * E + e] = a;
        g_la[b * E + e] = xla_logf(__fadd_rn(a, EPS));
    }
}

// ---------------------------------------------------------------------------
// K2: confusion scores, packed + SMEM row staging.
// 128 threads/CTA, one candidate per thread, 4 CTAs per batch row.
// Pass 1 reads global ONCE, stores ne = v+EPS into smem; pass 2 reads smem
// (no L2 latency). Arithmetic identical to R11 (Markstein CR division,
// packed Cephes log, NEON reduce).
// ---------------------------------------------------------------------------
__global__ __launch_bounds__(128, 6) void k_scores(const float* __restrict__ neg) {
    __shared__ u64 s_a64[E / 2], s_la64[E / 2];
    __shared__ u64 srow[32][128];    // [chunk][tid] -> conflict-free

    int b = blockIdx.x >> 2;
    int k = ((blockIdx.x & 3) << 7) + threadIdx.x;
    int tid = threadIdx.x;
    if (tid < E / 2) {
        const float* pa = &g_aw[b * E + 2 * tid];
        const float* pl = &g_la[b * E + 2 * tid];
        s_a64[tid]  = pk2(__ldg(pa), __ldg(pa + 1));
        s_la64[tid] = pk2(__ldg(pl), __ldg(pl + 1));
    }
    __syncthreads();

    const u64* row = (const u64*)(neg + ((size_t)b * K + k) * E);
    const u64 EPS2 = pk2(EPS, EPS);

    // pass 1: single global read; sum + stage ne into smem
    u64 acc01 = 0ull, acc23 = 0ull;
    #pragma unroll
    for (int c = 0; c < 16; c++) {
        ulonglong2 rv = __ldg((const ulonglong2*)(row + 2 * c));
        u64 ne01 = add2(rv.x, EPS2);
        u64 ne23 = add2(rv.y, EPS2);
        acc01 = add2(acc01, ne01);
        acc23 = add2(acc23, ne23);
        srow[2 * c][tid]     = ne01;
        srow[2 * c + 1][tid] = ne23;
    }
    float h02, h13;
    upk2(add2(acc01, acc23), h02, h13);
    float S = __fadd_rn(h02, h13);

    float yr = __frcp_rn(S);                  // correctly-rounded 1/S
    const u64 yy    = pk2(yr, yr);
    const u64 negS2 = pk2(-S, -S);
    const u64 NEG1  = pk2(-1.0f, -1.0f);

    // pass 2: smem reads, packed KL accumulation
    u64 k01 = 0ull, k23 = 0ull;
    #pragma unroll 4
    for (int c = 0; c < 16; c++) {
        u64 ne01 = srow[2 * c][tid];
        u64 ne23 = srow[2 * c + 1][tid];
        // Markstein correctly-rounded division by S
        u64 q01 = mul2(ne01, yy);
        q01 = fma2(fma2(negS2, q01, ne01), yy, q01);
        u64 q23 = mul2(ne23, yy);
        q23 = fma2(fma2(negS2, q23, ne23), yy, q23);

        u64 ln01 = xla_logf_x2(add2(q01, EPS2));
        u64 ln23 = xla_logf_x2(add2(q23, EPS2));

        u64 d01 = add2(s_la64[2 * c],     mul2(ln01, NEG1));  // la - ln
        u64 d23 = add2(s_la64[2 * c + 1], mul2(ln23, NEG1));
        k01 = add2(k01, mul2(s_a64[2 * c],     d01));
        k23 = add2(k23, mul2(s_a64[2 * c + 1], d23));
    }
    float g02, g13;
    upk2(add2(k01, k23), g02, g13);
    g_scores[b * K + k] = -__fadd_rn(g02, g13);
}

// ---------------------------------------------------------------------------
// K3: per-row top-64 via bitonic sort of 512 (desc, ties -> lower index).
// ---------------------------------------------------------------------------
__global__ __launch_bounds__(512) void k_topk(float* __restrict__ out_scores) {
    __shared__ float ss[K];
    __shared__ int   si[K];
    int b = blockIdx.x, tid = threadIdx.x;
    ss[tid] = g_scores[b * K + tid];
    si[tid] = tid;
    for (int sz = 2; sz <= K; sz <<= 1) {
        for (int j = sz >> 1; j > 0; j >>= 1) {
            __syncthreads();
            int ixj = tid ^ j;
            if (ixj > tid) {
                bool desc = ((tid & sz) == 0);
                float s1 = ss[tid], s2 = ss[ixj];
                int   i1 = si[tid], i2 = si[ixj];
                bool g = (s1 > s2) || (s1 == s2 && i1 < i2);
                if (g != desc) {
                    ss[tid] = s2; ss[ixj] = s1;
                    si[tid] = i2; si[ixj] = i1;
                }
            }
        }
    }
    __syncthreads();
    if (tid < TOPK) {
        out_scores[b * TOPK + tid] = ss[tid];
        g_idx[b * TOPK + tid]      = si[tid];
    }
}

// ---------------------------------------------------------------------------
// K4: gather (scalar, proven 68.4-68.9 us — best measured variant).
// ---------------------------------------------------------------------------
__global__ __launch_bounds__(128) void k_gather(
    const float* __restrict__ cand, float* __restrict__ out_hard)
{
    int blk = blockIdx.x;
    int b = blk >> 6, j = blk & (TOPK - 1);
    int idx = g_idx[b * TOPK + j];
    const float* __restrict__ src = cand + ((size_t)b * K + idx) * D;
    float* __restrict__ dst = out_hard + ((size_t)b * TOPK + j) * D;
    #pragma unroll
    for (int i = threadIdx.x; i < D; i += 128)
        dst[i] = __ldg(src + i);
}

// ---------------------------------------------------------------------------
extern "C" void kernel_launch(void* const* d_in, const int* in_sizes, int n_in,
                              void* d_out, int out_size) {
    const float* anchor = (const float*)d_in[0];  // (B, E)
    const float* neg    = (const float*)d_in[1];  // (B, K, E)
    const float* cand   = (const float*)d_in[2];  // (B, K, D)
    float* out        = (float*)d_out;
    float* out_hard   = out;                          // (B, TOPK, D)
    float* out_scores = out + (size_t)B * TOPK * D;   // (B, TOPK)

    k_anchor<<<4, 256>>>(anchor);
    k_scores<<<B * 4, 128>>>(neg);
    k_topk<<<B, 512>>>(out_scores);
    k_gather<<<B * TOPK, 128>>>(cand, out_hard);
}

// round 14
// speedup vs baseline: 1.2345x; 1.0943x over previous
#include <cuda_runtime.h>
#include <cstddef>
#include <cstdint>

#define EPS 1e-8f

static constexpr int B    = 1024;
static constexpr int K    = 512;
static constexpr int E    = 64;
static constexpr int D    = 769;
static constexpr int TOPK = 64;

typedef unsigned long long u64;

__device__ float g_aw[B * E];
__device__ float g_la[B * E];
__device__ float g_scores[B * K];
__device__ int   g_idx[B * TOPK];

// ---------------------------------------------------------------------------
// Packed f32x2 primitives — two independent IEEE rn f32 ops per instruction,
// bit-identical per lane to scalar __fadd_rn/__fmul_rn/fmaf.
// ---------------------------------------------------------------------------
__device__ __forceinline__ u64 pk2(float lo, float hi) {
    u64 r; asm("mov.b64 %0, {%1, %2};" : "=l"(r) : "f"(lo), "f"(hi)); return r;
}
__device__ __forceinline__ void upk2(u64 v, float& lo, float& hi) {
    asm("mov.b64 {%0, %1}, %2;" : "=f"(lo), "=f"(hi) : "l"(v));
}
__device__ __forceinline__ u64 add2(u64 a, u64 b) {
    u64 r; asm("add.rn.f32x2 %0, %1, %2;" : "=l"(r) : "l"(a), "l"(b)); return r;
}
__device__ __forceinline__ u64 mul2(u64 a, u64 b) {
    u64 r; asm("mul.rn.f32x2 %0, %1, %2;" : "=l"(r) : "l"(a), "l"(b)); return r;
}
__device__ __forceinline__ u64 fma2(u64 a, u64 b, u64 c) {
    u64 r; asm("fma.rn.f32x2 %0, %1, %2, %3;" : "=l"(r) : "l"(a), "l"(b), "l"(c)); return r;
}

// ---------------------------------------------------------------------------
// Scalar XLA-CPU log (Eigen plog / Cephes, no FMA) — proven. Anchor only.
// DO NOT MODIFY.
// ---------------------------------------------------------------------------
__device__ __forceinline__ float xla_logf(float xin) {
    float x = fmaxf(xin, __uint_as_float(0x00800000u));
    uint32_t bits = __float_as_uint(x);
    int emm0 = (int)(bits >> 23) - 126;
    float e = (float)emm0;
    float m = __uint_as_float((bits & 0x807fffffu) | 0x3f000000u);
    bool mask = m < __uint_as_float(0x3f3504f3u);
    float tmp = mask ? m : 0.0f;
    float xx = __fadd_rn(__fsub_rn(m, 1.0f), tmp);
    e = __fsub_rn(e, mask ? 1.0f : 0.0f);

    float z = __fmul_rn(xx, xx);
    float y = 7.0376836292e-2f;
    y = __fadd_rn(__fmul_rn(y, xx), -1.1514610310e-1f);
    y = __fadd_rn(__fmul_rn(y, xx),  1.1676998740e-1f);
    y = __fadd_rn(__fmul_rn(y, xx), -1.2420140846e-1f);
    y = __fadd_rn(__fmul_rn(y, xx),  1.4249322787e-1f);
    y = __fadd_rn(__fmul_rn(y, xx), -1.6668057665e-1f);
    y = __fadd_rn(__fmul_rn(y, xx),  2.0000714765e-1f);
    y = __fadd_rn(__fmul_rn(y, xx), -2.4999993993e-1f);
    y = __fadd_rn(__fmul_rn(y, xx),  3.3333331174e-1f);
    y = __fmul_rn(y, xx);
    y = __fmul_rn(y, z);
    y = __fadd_rn(y, __fmul_rn(e, -2.12194440e-4f));
    y = __fsub_rn(y, __fmul_rn(z, 0.5f));
    float r = __fadd_rn(xx, y);
    r = __fadd_rn(r, __fmul_rn(e, 0.693359375f));
    return r;
}

// ---------------------------------------------------------------------------
// Packed XLA-CPU log (R11/R13 form): bit-identical per lane to xla_logf for
// our inputs (>= 1e-8, normal; fmax clamp an identity, dropped). DO NOT MODIFY.
// ---------------------------------------------------------------------------
__device__ __forceinline__ u64 xla_logf_x2(u64 x01) {
    float x0, x1; upk2(x01, x0, x1);
    uint32_t b0 = __float_as_uint(x0), b1 = __float_as_uint(x1);
    int e0i = (int)(b0 >> 23) - 126;
    int e1i = (int)(b1 >> 23) - 126;
    float m0 = __uint_as_float((b0 & 0x807fffffu) | 0x3f000000u);
    float m1 = __uint_as_float((b1 & 0x807fffffu) | 0x3f000000u);
    const float SQ = __uint_as_float(0x3f3504f3u);
    bool k0 = m0 < SQ, k1 = m1 < SQ;
    float t0 = k0 ? m0 : 0.0f;
    float t1 = k1 ? m1 : 0.0f;
    if (k0) e0i -= 1;
    if (k1) e1i -= 1;
    u64 m01 = pk2(m0, m1);
    u64 t01 = pk2(t0, t1);
    u64 e01 = pk2((float)e0i, (float)e1i);

    u64 xx = add2(add2(m01, pk2(-1.0f, -1.0f)), t01);
    u64 z  = mul2(xx, xx);
    u64 y  = pk2(7.0376836292e-2f, 7.0376836292e-2f);
    y = add2(mul2(y, xx), pk2(-1.1514610310e-1f, -1.1514610310e-1f));
    y = add2(mul2(y, xx), pk2( 1.1676998740e-1f,  1.1676998740e-1f));
    y = add2(mul2(y, xx), pk2(-1.2420140846e-1f, -1.2420140846e-1f));
    y = add2(mul2(y, xx), pk2( 1.4249322787e-1f,  1.4249322787e-1f));
    y = add2(mul2(y, xx), pk2(-1.6668057665e-1f, -1.6668057665e-1f));
    y = add2(mul2(y, xx), pk2( 2.0000714765e-1f,  2.0000714765e-1f));
    y = add2(mul2(y, xx), pk2(-2.4999993993e-1f, -2.4999993993e-1f));
    y = add2(mul2(y, xx), pk2( 3.3333331174e-1f,  3.3333331174e-1f));
    y = mul2(y, xx);
    y = mul2(y, z);
    y = add2(y, mul2(e01, pk2(-2.12194440e-4f, -2.12194440e-4f)));
    y = add2(y, mul2(z,   pk2(-0.5f, -0.5f)));
    u64 r = add2(xx, y);
    r = add2(r, mul2(e01, pk2(0.693359375f, 0.693359375f)));
    return r;
}

#define NEON_HORIZ(a0, a1, a2, a3) __fadd_rn(__fadd_rn(a0, a2), __fadd_rn(a1, a3))

// ---------------------------------------------------------------------------
// K1: anchor rows (scalar, proven, unchanged).
// ---------------------------------------------------------------------------
__global__ __launch_bounds__(256) void k_anchor(const float* __restrict__ anchor) {
    int b = blockIdx.x * blockDim.x + threadIdx.x;
    if (b >= B) return;
    const float4* row = (const float4*)(anchor + b * E);
    float4 vv[16];
    float a0 = 0.f, a1 = 0.f, a2 = 0.f, a3 = 0.f;
    #pragma unroll
    for (int c = 0; c < 16; c++) {
        vv[c] = __ldg(row + c);
        a0 = __fadd_rn(a0, __fadd_rn(vv[c].x, EPS));
        a1 = __fadd_rn(a1, __fadd_rn(vv[c].y, EPS));
        a2 = __fadd_rn(a2, __fadd_rn(vv[c].z, EPS));
        a3 = __fadd_rn(a3, __fadd_rn(vv[c].w, EPS));
    }
    float S = NEON_HORIZ(a0, a1, a2, a3);
    const float* vf = (const float*)vv;
    #pragma unroll
    for (int e = 0; e < E; e++) {
        float a = __fdiv_rn(__fadd_rn(vf[e], EPS), S);
        g_aw[b * E + e] = a;
        g_la[b * E + e] = xla_logf(__fadd_rn(a, EPS));
    }
}

// ---------------------------------------------------------------------------
// K2: confusion scores. Cooperative COALESCED tile load with transpose into
// smem (each 128B line fetched exactly once), then per-thread arithmetic
// identical to R13 (sequential NEON-pair sum, Markstein CR div, packed
// Cephes log). 128 thr/CTA, 128 candidates/CTA, 4 CTAs per batch row.
// srow padded to 129 u64/chunk-row: coalesced LDG.128 + ~2-way STS,
// conflict-free LDS on the compute side.
// ---------------------------------------------------------------------------
__global__ __launch_bounds__(128, 6) void k_scores(const float* __restrict__ neg) {
    __shared__ u64 s_a64[E / 2], s_la64[E / 2];
    __shared__ u64 srow[32][129];    // [chunk][candidate], padded

    int b   = blockIdx.x >> 2;
    int k0  = (blockIdx.x & 3) << 7;          // tile base candidate
    int tid = threadIdx.x;
    if (tid < E / 2) {
        const float* pa = &g_aw[b * E + 2 * tid];
        const float* pl = &g_la[b * E + 2 * tid];
        s_a64[tid]  = pk2(__ldg(pa), __ldg(pa + 1));
        s_la64[tid] = pk2(__ldg(pl), __ldg(pl + 1));
    }

    const u64 EPS2 = pk2(EPS, EPS);

    // ---- cooperative coalesced load + transpose (adds EPS, packed) -------
    const float4* tile = (const float4*)(neg + ((size_t)b * K + k0) * E);
    #pragma unroll
    for (int i = 0; i < 16; i++) {
        int f = tid + (i << 7);                // float4 index in tile
        int r  = f >> 4;                       // candidate row 0..127
        int c2 = f & 15;                       // float4 slot -> chunks 2c2,2c2+1
        float4 v = __ldg(tile + f);
        u64 lo, hi;
        asm("mov.b64 %0, {%1, %2};" : "=l"(lo) : "f"(v.x), "f"(v.y));
        asm("mov.b64 %0, {%1, %2};" : "=l"(hi) : "f"(v.z), "f"(v.w));
        srow[2 * c2][r]     = add2(lo, EPS2);
        srow[2 * c2 + 1][r] = add2(hi, EPS2);
    }
    __syncthreads();

    // ---- pass 1: row sum (sequential packed adds, exact reference order) -
    u64 acc01 = 0ull, acc23 = 0ull;
    #pragma unroll
    for (int c = 0; c < 16; c++) {
        acc01 = add2(acc01, srow[2 * c][tid]);
        acc23 = add2(acc23, srow[2 * c + 1][tid]);
    }
    float h02, h13;
    upk2(add2(acc01, acc23), h02, h13);
    float S = __fadd_rn(h02, h13);

    float yr = __frcp_rn(S);                   // correctly-rounded 1/S
    const u64 yy    = pk2(yr, yr);
    const u64 negS2 = pk2(-S, -S);
    const u64 NEG1  = pk2(-1.0f, -1.0f);

    // ---- pass 2: packed KL accumulation ----------------------------------
    u64 k01 = 0ull, k23 = 0ull;
    #pragma unroll 4
    for (int c = 0; c < 16; c++) {
        u64 ne01 = srow[2 * c][tid];
        u64 ne23 = srow[2 * c + 1][tid];
        // Markstein correctly-rounded division by S
        u64 q01 = mul2(ne01, yy);
        q01 = fma2(fma2(negS2, q01, ne01), yy, q01);
        u64 q23 = mul2(ne23, yy);
        q23 = fma2(fma2(negS2, q23, ne23), yy, q23);

        u64 ln01 = xla_logf_x2(add2(q01, EPS2));
        u64 ln23 = xla_logf_x2(add2(q23, EPS2));

        u64 d01 = add2(s_la64[2 * c],     mul2(ln01, NEG1));   // la - ln
        u64 d23 = add2(s_la64[2 * c + 1], mul2(ln23, NEG1));
        k01 = add2(k01, mul2(s_a64[2 * c],     d01));
        k23 = add2(k23, mul2(s_a64[2 * c + 1], d23));
    }
    float g02, g13;
    upk2(add2(k01, k23), g02, g13);
    g_scores[b * K + k0 + tid] = -__fadd_rn(g02, g13);
}

// ---------------------------------------------------------------------------
// K3: per-row top-64 via bitonic sort of 512 (desc, ties -> lower index).
// ---------------------------------------------------------------------------
__global__ __launch_bounds__(512) void k_topk(float* __restrict__ out_scores) {
    __shared__ float ss[K];
    __shared__ int   si[K];
    int b = blockIdx.x, tid = threadIdx.x;
    ss[tid] = g_scores[b * K + tid];
    si[tid] = tid;
    for (int sz = 2; sz <= K; sz <<= 1) {
        for (int j = sz >> 1; j > 0; j >>= 1) {
            __syncthreads();
            int ixj = tid ^ j;
            if (ixj > tid) {
                bool desc = ((tid & sz) == 0);
                float s1 = ss[tid], s2 = ss[ixj];
                int   i1 = si[tid], i2 = si[ixj];
                bool g = (s1 > s2) || (s1 == s2 && i1 < i2);
                if (g != desc) {
                    ss[tid] = s2; ss[ixj] = s1;
                    si[tid] = i2; si[ixj] = i1;
                }
            }
        }
    }
    __syncthreads();
    if (tid < TOPK) {
        out_scores[b * TOPK + tid] = ss[tid];
        g_idx[b * TOPK + tid]      = si[tid];
    }
}

// ---------------------------------------------------------------------------
// K4: gather (scalar, proven best variant — 68.4 us).
// ---------------------------------------------------------------------------
__global__ __launch_bounds__(128) void k_gather(
    const float* __restrict__ cand, float* __restrict__ out_hard)
{
    int blk = blockIdx.x;
    int b = blk >> 6, j = blk & (TOPK - 1);
    int idx = g_idx[b * TOPK + j];
    const float* __restrict__ src = cand + ((size_t)b * K + idx) * D;
    float* __restrict__ dst = out_hard + ((size_t)b * TOPK + j) * D;
    #pragma unroll
    for (int i = threadIdx.x; i < D; i += 128)
        dst[i] = __ldg(src + i);
}

// ---------------------------------------------------------------------------
extern "C" void kernel_launch(void* const* d_in, const int* in_sizes, int n_in,
                              void* d_out, int out_size) {
    const float* anchor = (const float*)d_in[0];  // (B, E)
    const float* neg    = (const float*)d_in[1];  // (B, K, E)
    const float* cand   = (const float*)d_in[2];  // (B, K, D)
    float* out        = (float*)d_out;
    float* out_hard   = out;                          // (B, TOPK, D)
    float* out_scores = out + (size_t)B * TOPK * D;   // (B, TOPK)

    k_anchor<<<4, 256>>>(anchor);
    k_scores<<<B * 4, 128>>>(neg);
    k_topk<<<B, 512>>>(out_scores);
    k_gather<<<B * TOPK, 128>>>(cand, out_hard);
}